// round 5
// baseline (speedup 1.0000x reference)
#include <cuda_runtime.h>
#include <cuda_bf16.h>
#include <cstdint>

namespace {

constexpr int S = 8192;          // sequence length per batch row
constexpr int T = 32768;         // 4 * 8192 tokens
constexpr int H = 64;            // hash dim (K of GEMM)
constexpr int MOUT = 1024;       // model dim (N of GEMM)
constexpr long long HASH_MULT = 92821;
constexpr long long NUM_BUCKETS = 2000003;

constexpr int BM = 64;           // tokens per block
constexpr int BN = 64;           // output cols per inner iteration
constexpr int NT = MOUT / BN;    // 16 N-tiles
constexpr int AST = H + 8;       // padded smem row stride (72 bf16 = 144 B)

// proj_w pre-converted to bf16, row-major [MOUT][H] (128 KB: L1-resident)
__device__ __nv_bfloat16 g_wbf16[MOUT * H];

// Convert proj_w (f32) -> g_wbf16 once per launch. 65536 elems, 8 per thread.
__global__ void convert_w_kernel(const float* __restrict__ proj) {
    int base = (blockIdx.x * blockDim.x + threadIdx.x) * 8;
    float4 v0 = *reinterpret_cast<const float4*>(proj + base);
    float4 v1 = *reinterpret_cast<const float4*>(proj + base + 4);
    __nv_bfloat162 b[4];
    b[0] = __floats2bfloat162_rn(v0.x, v0.y);
    b[1] = __floats2bfloat162_rn(v0.z, v0.w);
    b[2] = __floats2bfloat162_rn(v1.x, v1.y);
    b[3] = __floats2bfloat162_rn(v1.z, v1.w);
    *reinterpret_cast<uint4*>(g_wbf16 + base) = *reinterpret_cast<uint4*>(b);
}

__device__ __forceinline__ void ldmatrix_x4(uint32_t r[4], uint32_t addr) {
    asm volatile(
        "ldmatrix.sync.aligned.m8n8.x4.shared.b16 {%0,%1,%2,%3}, [%4];"
        : "=r"(r[0]), "=r"(r[1]), "=r"(r[2]), "=r"(r[3])
        : "r"(addr));
}

__device__ __forceinline__ void mma_bf16(float c[4], const uint32_t a[4],
                                         uint32_t b0, uint32_t b1) {
    asm volatile(
        "mma.sync.aligned.m16n8k16.row.col.f32.bf16.bf16.f32 "
        "{%0,%1,%2,%3}, {%4,%5,%6,%7}, {%8,%9}, {%0,%1,%2,%3};"
        : "+f"(c[0]), "+f"(c[1]), "+f"(c[2]), "+f"(c[3])
        : "r"(a[0]), "r"(a[1]), "r"(a[2]), "r"(a[3]), "r"(b0), "r"(b1));
}

__global__ __launch_bounds__(256, 4)
void bigram_kernel(const int* __restrict__ ids, const float* __restrict__ table,
                   float* __restrict__ out) {
    __shared__ __align__(16) __nv_bfloat16 As[BM][AST];    // emb tile (M x K)

    const int tid = threadIdx.x;
    const int warp = tid >> 5;
    const int lane = tid & 31;
    const int wm = warp >> 2;   // 0..1 : M position (32 rows each)
    const int wn = warp & 3;    // 0..3 : N position (16 cols each)
    const int t0 = blockIdx.x * BM;

    // ---- Local layout detection (no extra kernel) ----
    // Odd words at indices 1..127 are in-bounds for both layouts. All-zero
    // <=> int64 layout (token values < 2^31, nonnegative). For the int32
    // layout these are token ids; 64 simultaneous zeros cannot happen.
    const int probe = ids[2 * (tid & 63) + 1];
    const int id_stride = __syncthreads_or(probe) ? 1 : 2;

    // ---- Hash + gather embedding tile (once per block) ----
    {
        const int tl = tid >> 2;           // local token 0..63
        const int q = tid & 3;             // 16-float quarter of the row
        const int t = t0 + tl;
        long long cur = ids[(long long)t * id_stride];
        long long prev = ((t & (S - 1)) == 0)
                             ? 0
                             : (long long)ids[(long long)(t - 1) * id_stride];
        long long h = (prev * HASH_MULT + cur) % NUM_BUCKETS;
        const float4* src =
            reinterpret_cast<const float4*>(table + h * H + q * 16);
        __nv_bfloat162* dst = reinterpret_cast<__nv_bfloat162*>(&As[tl][q * 16]);
#pragma unroll
        for (int i = 0; i < 4; i++) {
            float4 v = src[i];
            dst[2 * i]     = __floats2bfloat162_rn(v.x, v.y);
            dst[2 * i + 1] = __floats2bfloat162_rn(v.z, v.w);
        }
    }
    __syncthreads();  // the only barrier in the kernel

    // ---- Load A fragments once; reused across all 16 N-tiles ----
    uint32_t afrag[2][4][4];  // [m-subtile][k-step][reg]
#pragma unroll
    for (int mi = 0; mi < 2; mi++) {
#pragma unroll
        for (int ks = 0; ks < 4; ks++) {
            const int row = wm * 32 + mi * 16 + (lane & 15);
            const int col = ks * 16 + ((lane >> 4) << 3);
            uint32_t addr = (uint32_t)__cvta_generic_to_shared(&As[row][col]);
            ldmatrix_x4(afrag[mi][ks], addr);
        }
    }

    // ---- B fragments come straight from global (L1-resident 128 KB) ----
    // Fragment element: row = nt*64 + wn*16 + ni*8 + (lane>>2),
    //                   k   = ks*16 + (lane&3)*2  (+8 for b1)
    const __nv_bfloat16* bbase =
        g_wbf16 + (wn * 16 + (lane >> 2)) * H + (lane & 3) * 2;
    const int row_base = t0 + wm * 32 + (lane >> 2);
    float* out_base = out + (long long)row_base * MOUT + wn * 16 + (lane & 3) * 2;

    for (int nt = 0; nt < NT; nt++) {
        float c[2][2][4];
#pragma unroll
        for (int mi = 0; mi < 2; mi++)
#pragma unroll
            for (int ni = 0; ni < 2; ni++)
#pragma unroll
                for (int r = 0; r < 4; r++) c[mi][ni][r] = 0.0f;

        const __nv_bfloat16* bp = bbase + nt * (BN * H);
#pragma unroll
        for (int ks = 0; ks < 4; ks++) {
#pragma unroll
            for (int ni = 0; ni < 2; ni++) {
                const __nv_bfloat16* p = bp + ni * (8 * H) + ks * 16;
                uint32_t b0 = *reinterpret_cast<const uint32_t*>(p);
                uint32_t b1 = *reinterpret_cast<const uint32_t*>(p + 8);
                mma_bf16(c[0][ni], afrag[0][ks], b0, b1);
                mma_bf16(c[1][ni], afrag[1][ks], b0, b1);
            }
        }

        // ---- Epilogue: evict-first f32 stores ----
#pragma unroll
        for (int mi = 0; mi < 2; mi++) {
#pragma unroll
            for (int ni = 0; ni < 2; ni++) {
                float* p = out_base + (long long)(mi * 16) * MOUT + nt * BN + ni * 8;
                __stcs(reinterpret_cast<float2*>(p),
                       make_float2(c[mi][ni][0], c[mi][ni][1]));
                __stcs(reinterpret_cast<float2*>(p + (long long)8 * MOUT),
                       make_float2(c[mi][ni][2], c[mi][ni][3]));
            }
        }
    }
}

}  // namespace

extern "C" void kernel_launch(void* const* d_in, const int* in_sizes, int n_in,
                              void* d_out, int out_size) {
    const int* ids = nullptr;
    const float* table = nullptr;
    const float* proj = nullptr;
    for (int i = 0; i < n_in; i++) {
        if (in_sizes[i] == T) ids = (const int*)d_in[i];
        else if (in_sizes[i] == (int)(NUM_BUCKETS * H)) table = (const float*)d_in[i];
        else if (in_sizes[i] == MOUT * H) proj = (const float*)d_in[i];
    }

    convert_w_kernel<<<MOUT * H / (256 * 8), 256>>>(proj);
    bigram_kernel<<<T / BM, 256>>>(ids, table, (float*)d_out);
}

// round 6
// speedup vs baseline: 1.6806x; 1.6806x over previous
#include <cuda_runtime.h>
#include <cuda_bf16.h>
#include <cstdint>

namespace {

constexpr int S = 8192;          // sequence length per batch row
constexpr int T = 32768;         // 4 * 8192 tokens
constexpr int H = 64;            // hash dim (K of GEMM)
constexpr int MOUT = 1024;       // model dim (N of GEMM)
constexpr long long HASH_MULT = 92821;
constexpr long long NUM_BUCKETS = 2000003;

constexpr int BM = 64;           // tokens per block
constexpr int BN = 64;           // output cols per inner iteration
constexpr int NT = MOUT / BN;    // 16 N-tiles
constexpr int AST = H + 8;       // padded smem row stride (72 bf16 = 144 B)

// proj_w pre-converted to bf16 with PERMUTED rows, row-major [MOUT][H].
// Logical output col L lives at row perm(L), where within each 16-row group
//   p(L16) = (L16 & 2) * 4 + ((L16 >> 2) & 3) * 2 + (L16 & 1)
// This makes each MMA lane's 4 accumulators cover 4 CONSECUTIVE logical
// columns, so the epilogue can use fully-formed STG.128 stores.
__device__ __nv_bfloat16 g_wbf16[MOUT * H];

// Convert + permute proj_w (f32) -> g_wbf16. 65536 elems, 8 per thread
// (all 8 within one source row since H=64 and base is a multiple of 8).
__global__ void convert_w_kernel(const float* __restrict__ proj) {
    int base = (blockIdx.x * blockDim.x + threadIdx.x) * 8;
    int row = base >> 6;          // logical output column L
    int col = base & 63;          // position within the H=64 row
    int l16 = row & 15;
    int prow = (row & ~15) + ((l16 & 2) << 2) + (((l16 >> 2) & 3) << 1) + (l16 & 1);

    float4 v0 = *reinterpret_cast<const float4*>(proj + base);
    float4 v1 = *reinterpret_cast<const float4*>(proj + base + 4);
    __nv_bfloat162 b[4];
    b[0] = __floats2bfloat162_rn(v0.x, v0.y);
    b[1] = __floats2bfloat162_rn(v0.z, v0.w);
    b[2] = __floats2bfloat162_rn(v1.x, v1.y);
    b[3] = __floats2bfloat162_rn(v1.z, v1.w);
    *reinterpret_cast<uint4*>(g_wbf16 + prow * H + col) =
        *reinterpret_cast<uint4*>(b);
}

__device__ __forceinline__ void ldmatrix_x4(uint32_t r[4], uint32_t addr) {
    asm volatile(
        "ldmatrix.sync.aligned.m8n8.x4.shared.b16 {%0,%1,%2,%3}, [%4];"
        : "=r"(r[0]), "=r"(r[1]), "=r"(r[2]), "=r"(r[3])
        : "r"(addr));
}

__device__ __forceinline__ void mma_bf16(float c[4], const uint32_t a[4],
                                         uint32_t b0, uint32_t b1) {
    asm volatile(
        "mma.sync.aligned.m16n8k16.row.col.f32.bf16.bf16.f32 "
        "{%0,%1,%2,%3}, {%4,%5,%6,%7}, {%8,%9}, {%0,%1,%2,%3};"
        : "+f"(c[0]), "+f"(c[1]), "+f"(c[2]), "+f"(c[3])
        : "r"(a[0]), "r"(a[1]), "r"(a[2]), "r"(a[3]), "r"(b0), "r"(b1));
}

__global__ __launch_bounds__(256, 4)
void bigram_kernel(const int* __restrict__ ids, const float* __restrict__ table,
                   float* __restrict__ out) {
    __shared__ __align__(16) __nv_bfloat16 As[BM][AST];    // emb tile (M x K)
    __shared__ __align__(16) __nv_bfloat16 Ws[2][BN][AST]; // ping-pong W (N x K)

    const int tid = threadIdx.x;
    const int warp = tid >> 5;
    const int lane = tid & 31;
    const int wm = warp >> 1;   // 0..3 : M position (16 rows each)
    const int wn = warp & 1;    // 0..1 : N position (32 cols each)
    const int t0 = blockIdx.x * BM;

    // ---- Local layout detection (no extra kernel) ----
    const int probe = ids[2 * (tid & 63) + 1];
    const int id_stride = __syncthreads_or(probe) ? 1 : 2;

    // ---- Hash + gather embedding tile (once per block) ----
    {
        const int tl = tid >> 2;           // local token 0..63
        const int q = tid & 3;             // 16-float quarter of the row
        const int t = t0 + tl;
        long long cur = ids[(long long)t * id_stride];
        long long prev = ((t & (S - 1)) == 0)
                             ? 0
                             : (long long)ids[(long long)(t - 1) * id_stride];
        long long h = (prev * HASH_MULT + cur) % NUM_BUCKETS;
        const float4* src =
            reinterpret_cast<const float4*>(table + h * H + q * 16);
        __nv_bfloat162* dst = reinterpret_cast<__nv_bfloat162*>(&As[tl][q * 16]);
#pragma unroll
        for (int i = 0; i < 4; i++) {
            float4 v = src[i];
            dst[2 * i]     = __floats2bfloat162_rn(v.x, v.y);
            dst[2 * i + 1] = __floats2bfloat162_rn(v.z, v.w);
        }
    }

    // ---- Prefetch W tile 0 into registers (overlaps with gather) ----
    const int j0 = tid;                 // uint4 index 0..255
    const int j1 = tid + 256;           // uint4 index 256..511
    const int r0 = j0 >> 3, c0 = (j0 & 7) * 8;
    const int r1 = j1 >> 3, c1 = (j1 & 7) * 8;
    uint4 w0 = *reinterpret_cast<const uint4*>(g_wbf16 + r0 * H + c0);
    uint4 w1 = *reinterpret_cast<const uint4*>(g_wbf16 + r1 * H + c1);

    __syncthreads();  // As tile complete

    // ---- Load A fragments once; reused across all 16 N-tiles ----
    uint32_t afrag[4][4];  // [k-step][reg]
#pragma unroll
    for (int ks = 0; ks < 4; ks++) {
        const int row = wm * 16 + (lane & 15);
        const int col = ks * 16 + ((lane >> 4) << 3);
        uint32_t addr = (uint32_t)__cvta_generic_to_shared(&As[row][col]);
        ldmatrix_x4(afrag[ks], addr);
    }

    const int b_row = wn * 32 + (lane >> 2);
    const int b_col = (lane & 3) * 2;
    const int row_out = t0 + wm * 16 + (lane >> 2);
    // per-lane contiguous 4-col base thanks to the W permutation
    float* out_lane = out + (long long)row_out * MOUT + wn * 32 + (lane & 3) * 4;

    for (int nt = 0; nt < NT; nt++) {
        const int buf = nt & 1;
        // ---- Commit prefetched W tile to smem ----
        *reinterpret_cast<uint4*>(&Ws[buf][r0][c0]) = w0;
        *reinterpret_cast<uint4*>(&Ws[buf][r1][c1]) = w1;
        __syncthreads();

        // ---- Issue next tile's loads early (latency hidden by MMA) ----
        if (nt + 1 < NT) {
            w0 = *reinterpret_cast<const uint4*>(
                g_wbf16 + ((nt + 1) * BN + r0) * H + c0);
            w1 = *reinterpret_cast<const uint4*>(
                g_wbf16 + ((nt + 1) * BN + r1) * H + c1);
        }

        // ---- MMA: warp computes 16 x 32 of this 64-col tile ----
        float c[4][4];
#pragma unroll
        for (int ni = 0; ni < 4; ni++)
#pragma unroll
            for (int r = 0; r < 4; r++) c[ni][r] = 0.0f;

#pragma unroll
        for (int ks = 0; ks < 4; ks++) {
#pragma unroll
            for (int ni = 0; ni < 4; ni++) {
                uint32_t b0 = *reinterpret_cast<const uint32_t*>(
                    &Ws[buf][b_row + ni * 8][ks * 16 + b_col]);
                uint32_t b1 = *reinterpret_cast<const uint32_t*>(
                    &Ws[buf][b_row + ni * 8][ks * 16 + b_col + 8]);
                mma_bf16(c[ni], afrag[ks], b0, b1);
            }
        }

        // ---- Epilogue: 4 fully-coalesced STG.128 per warp ----
        // logical cols (per permutation): half h covers wn*32 + h*16 + 4q + {0..3}
        //   +0: c[2h][r], +1: c[2h][r+1], +2: c[2h+1][r], +3: c[2h+1][r+1]
#pragma unroll
        for (int h = 0; h < 2; h++) {
            float* p = out_lane + nt * BN + h * 16;
            *reinterpret_cast<float4*>(p) =
                make_float4(c[2 * h][0], c[2 * h][1], c[2 * h + 1][0], c[2 * h + 1][1]);
            *reinterpret_cast<float4*>(p + (long long)8 * MOUT) =
                make_float4(c[2 * h][2], c[2 * h][3], c[2 * h + 1][2], c[2 * h + 1][3]);
        }
    }
}

}  // namespace

extern "C" void kernel_launch(void* const* d_in, const int* in_sizes, int n_in,
                              void* d_out, int out_size) {
    const int* ids = nullptr;
    const float* table = nullptr;
    const float* proj = nullptr;
    for (int i = 0; i < n_in; i++) {
        if (in_sizes[i] == T) ids = (const int*)d_in[i];
        else if (in_sizes[i] == (int)(NUM_BUCKETS * H)) table = (const float*)d_in[i];
        else if (in_sizes[i] == MOUT * H) proj = (const float*)d_in[i];
    }

    convert_w_kernel<<<MOUT * H / (256 * 8), 256>>>(proj);
    bigram_kernel<<<T / BM, 256>>>(ids, table, (float*)d_out);
}